// round 13
// baseline (speedup 1.0000x reference)
#include <cuda_runtime.h>

// Denoise_17669495455833 — batched 1-D FISTA QP, 2 passes, one warp per 512-row.
// R6: FFMA2-packed math (valid PTX only: fma/mul/add.rn.f32x2), scalar FMNMX
//     clamps. Software-pipelined halo exchange: boundary pairs updated first,
//     next-iter SHFLs issued mid-body, middle pairs cover SHFL latency.

#define N_ITERS  100
#define ROWLEN   512
#define EPT      16
#define NP       8            // packed pairs per thread
#define TPB      128

constexpr float STEP = 1.0f / 322.0f;
constexpr float CBc  = 2.0f * STEP;                         // y coefficient
constexpr float CCc  = 20.0f * STEP;
constexpr float C0c  = -CCc;                                // z[i+-2]
constexpr float C1c  = 4.0f * CCc;                          // z[i+-1]
constexpr float C2c  = (1.0f - 2.0f * STEP) - 6.0f * CCc;   // z[i]

// ---- compile-time FISTA momentum coefficients ck = (t-1)/t_next, packed ----
constexpr double csqrt(double x) {
    double g = x > 1.0 ? x : 1.0;
    for (int i = 0; i < 48; ++i) g = 0.5 * (g + x / g);
    return g;
}
constexpr unsigned long long dup_pack(float f) {
    unsigned int b = __builtin_bit_cast(unsigned int, f);
    return (unsigned long long)b | ((unsigned long long)b << 32);
}
struct CkTableP {
    unsigned long long v[N_ITERS];
    constexpr CkTableP() : v{} {
        double t = 1.0;
        for (int i = 0; i < N_ITERS; ++i) {
            double tn = 0.5 * (1.0 + csqrt(1.0 + 4.0 * t * t));
            v[i] = dup_pack((float)((t - 1.0) / tn));
            t = tn;
        }
    }
};
__constant__ CkTableP CKTABP = CkTableP();

using u64 = unsigned long long;

__device__ __forceinline__ u64 pk2(float lo, float hi) {
    u64 r; asm("mov.b64 %0,{%1,%2};" : "=l"(r) : "f"(lo), "f"(hi)); return r;
}
__device__ __forceinline__ void upk2(u64 v, float& lo, float& hi) {
    asm("mov.b64 {%0,%1},%2;" : "=f"(lo), "=f"(hi) : "l"(v));
}
__device__ __forceinline__ u64 f2fma(u64 a, u64 b, u64 c) {   // a*b + c (packed)
    u64 d; asm("fma.rn.f32x2 %0,%1,%2,%3;" : "=l"(d) : "l"(a), "l"(b), "l"(c)); return d;
}
__device__ __forceinline__ u64 f2mul(u64 a, u64 b) {
    u64 d; asm("mul.rn.f32x2 %0,%1,%2;" : "=l"(d) : "l"(a), "l"(b)); return d;
}

// stencil + clamp + momentum for one packed pair
#define UPD(j, Pm2, Pm1, Pc, Pp1, Pp2)                                   \
    do {                                                                 \
        u64 v = f2fma(C0P, (Pm2), ycP[j]);                               \
        v     = f2fma(C1P, (Pm1), v);                                    \
        v     = f2fma(C2P, (Pc),  v);                                    \
        v     = f2fma(C1P, (Pp1), v);                                    \
        v     = f2fma(C0P, (Pp2), v);                                    \
        float vl, vh, yl, yh;                                            \
        upk2(v, vl, vh);                                                 \
        upk2(ysP[j], yl, yh);                                            \
        vl = fminf(fmaxf(vl, 0.0f), yl);                                 \
        vh = fminf(fmaxf(vh, 0.0f), yh);                                 \
        u64 xn = pk2(vl, vh);                                            \
        u64 dd = f2fma(xP[j], M1P, xn);                                  \
        zP[j]  = f2fma(ckP, dd, xn);                                     \
        xP[j]  = xn;                                                     \
    } while (0)

__device__ __forceinline__ void fista_pass(const u64 ysP[NP], const u64 ycP[NP],
                                           u64 xP[NP], int lane)
{
    const bool L = (lane == 0), R = (lane == 31);
    const u64 C0P = pk2(C0c, C0c);
    const u64 C1P = pk2(C1c, C1c);
    const u64 C2P = pk2(C2c, C2c);
    const u64 M1P = pk2(-1.0f, -1.0f);

    // proj(y) onto [0, y] == y identically (min(max(y,0),y) = y for all y)
    u64 zP[NP];
#pragma unroll
    for (int j = 0; j < NP; ++j) { xP[j] = ysP[j]; zP[j] = ysP[j]; }

    // prologue halo exchange (for iteration 0)
    float zm1, zm2, zp16, zp17;
    {
        float z0, z8, z1, z9, z6, z14, z7, z15;
        upk2(zP[0], z0, z8); upk2(zP[1], z1, z9);
        upk2(zP[6], z6, z14); upk2(zP[7], z7, z15);
        zm1  = __shfl_up_sync  (0xffffffffu, z15, 1);
        zm2  = __shfl_up_sync  (0xffffffffu, z14, 1);
        zp16 = __shfl_down_sync(0xffffffffu, z0, 1);
        zp17 = __shfl_down_sync(0xffffffffu, z1, 1);
        float a = z0 - z1, g1 = z0 + a, g2 = g1 + a;
        if (L) { zm1 = g1; zm2 = g2; }
        float b = z15 - z14, h1 = z15 + b, h2 = h1 + b;
        if (R) { zp16 = h1; zp17 = h2; }
    }

#pragma unroll 1
    for (int it = 0; it < N_ITERS; ++it) {
        const u64 ckP = CKTABP.v[it];

        // seam pairs from current z + halos
        float z0, z8, z1, z9, z6, z14, z7, z15;
        upk2(zP[0], z0, z8); upk2(zP[1], z1, z9);
        upk2(zP[6], z6, z14); upk2(zP[7], z7, z15);
        const u64 PP0 = pk2(zm2, z6);     // (z[-2], z[6])
        const u64 PP1 = pk2(zm1, z7);     // (z[-1], z[7])
        const u64 PPa = pk2(z8, zp16);    // (z[8],  z[16])
        const u64 PPb = pk2(z9, zp17);    // (z[9],  z[17])

        // snapshot old z pairs (register renames)
        const u64 o0 = zP[0], o1 = zP[1], o2 = zP[2], o3 = zP[3];
        const u64 o4 = zP[4], o5 = zP[5], o6 = zP[6], o7 = zP[7];

        // 1) boundary pairs (consume halos)
        UPD(0, PP0, PP1, o0, o1, o2);
        UPD(1, PP1, o0,  o1, o2, o3);
        UPD(6, o4,  o5,  o6, o7, PPa);
        UPD(7, o5,  o6,  o7, PPa, PPb);

        // 2) issue next-iteration halo exchange NOW (uses new zP0,1,6,7);
        //    middle-pair math below covers the SHFL latency
        {
            float n0, n8, n1, n9, n6, n14, n7, n15;
            upk2(zP[0], n0, n8); upk2(zP[1], n1, n9);
            upk2(zP[6], n6, n14); upk2(zP[7], n7, n15);
            zm1  = __shfl_up_sync  (0xffffffffu, n15, 1);
            zm2  = __shfl_up_sync  (0xffffffffu, n14, 1);
            zp16 = __shfl_down_sync(0xffffffffu, n0, 1);
            zp17 = __shfl_down_sync(0xffffffffu, n1, 1);
            float a = n0 - n1, g1 = n0 + a, g2 = g1 + a;
            if (L) { zm1 = g1; zm2 = g2; }
            float b = n15 - n14, h1 = n15 + b, h2 = h1 + b;
            if (R) { zp16 = h1; zp17 = h2; }
        }

        // 3) middle pairs (independent of halos)
        UPD(2, o0, o1, o2, o3, o4);
        UPD(3, o1, o2, o3, o4, o5);
        UPD(4, o2, o3, o4, o5, o6);
        UPD(5, o3, o4, o5, o6, o7);
    }
}

__global__ void __launch_bounds__(TPB, 5)
denoise_fista_kernel(const float* __restrict__ in, float* __restrict__ out, int nrows)
{
    const int warp = blockIdx.x * (TPB / 32) + (threadIdx.x >> 5);
    const int lane = threadIdx.x & 31;
    if (warp >= nrows) return;

    const float4* src = reinterpret_cast<const float4*>(in + (size_t)warp * ROWLEN + lane * EPT);
    float ys[EPT];
    {
        float4 a = src[0], b = src[1], c = src[2], d4 = src[3];
        ys[0] = a.x;  ys[1] = a.y;  ys[2]  = a.z;  ys[3]  = a.w;
        ys[4] = b.x;  ys[5] = b.y;  ys[6]  = b.z;  ys[7]  = b.w;
        ys[8] = c.x;  ys[9] = c.y;  ys[10] = c.z;  ys[11] = c.w;
        ys[12] = d4.x; ys[13] = d4.y; ys[14] = d4.z; ys[15] = d4.w;
    }

    u64 ysP[NP], ycP[NP];
    const u64 CBP = pk2(CBc, CBc);
#pragma unroll
    for (int j = 0; j < NP; ++j) {
        ysP[j] = pk2(ys[j], ys[j + 8]);
        ycP[j] = f2mul(CBP, ysP[j]);
    }

    u64 xP[NP];
    fista_pass(ysP, ycP, xP, lane);       // pass 1: y = input

    u64 ysP2[NP], ycP2[NP];
#pragma unroll
    for (int j = 0; j < NP; ++j) {
        ysP2[j] = xP[j];
        ycP2[j] = f2mul(CBP, xP[j]);
    }
    fista_pass(ysP2, ycP2, xP, lane);     // pass 2: y = pass-1 output

    float xo[EPT];
#pragma unroll
    for (int j = 0; j < NP; ++j) {
        float lo, hi;
        upk2(xP[j], lo, hi);
        xo[j] = lo; xo[j + 8] = hi;
    }

    float4* dst = reinterpret_cast<float4*>(out + (size_t)warp * ROWLEN + lane * EPT);
    float4 a, b, c, d4;
    a.x = xo[0];  a.y = xo[1];  a.z = xo[2];   a.w = xo[3];
    b.x = xo[4];  b.y = xo[5];  b.z = xo[6];   b.w = xo[7];
    c.x = xo[8];  c.y = xo[9];  c.z = xo[10];  c.w = xo[11];
    d4.x = xo[12]; d4.y = xo[13]; d4.z = xo[14]; d4.w = xo[15];
    dst[0] = a; dst[1] = b; dst[2] = c; dst[3] = d4;
}

extern "C" void kernel_launch(void* const* d_in, const int* in_sizes, int n_in,
                              void* d_out, int out_size)
{
    const float* in  = (const float*)d_in[0];
    float*       out = (float*)d_out;
    const int nrows  = in_sizes[0] / ROWLEN;            // 16384
    const int rows_per_block = TPB / 32;                // 4
    const int grid = (nrows + rows_per_block - 1) / rows_per_block;
    denoise_fista_kernel<<<grid, TPB>>>(in, out, nrows);
}

// round 15
// speedup vs baseline: 1.0103x; 1.0103x over previous
#include <cuda_runtime.h>

// Denoise_17669495455833 — batched 1-D FISTA QP, 2 passes, one warp per 512-row.
// R7: RF-banking-aware packed math. Symmetric stencil via add.rn.f32x2 (rt2)
//     + 3 FFMA2; momentum as mul2(-ck,x)+fma2(1+ck,xn,t). Simple R4 loop.

#define N_ITERS  100
#define ROWLEN   512
#define EPT      16
#define NP       8            // packed pairs per thread
#define TPB      128

constexpr float STEP = 1.0f / 322.0f;
constexpr float CBc  = 2.0f * STEP;                         // y coefficient
constexpr float CCc  = 20.0f * STEP;
constexpr float C0c  = -CCc;                                // z[i+-2]
constexpr float C1c  = 4.0f * CCc;                          // z[i+-1]
constexpr float C2c  = (1.0f - 2.0f * STEP) - 6.0f * CCc;   // z[i]

// ---- compile-time FISTA momentum coefficients, packed: (1+ck) and (-ck) ----
constexpr double csqrt(double x) {
    double g = x > 1.0 ? x : 1.0;
    for (int i = 0; i < 48; ++i) g = 0.5 * (g + x / g);
    return g;
}
constexpr unsigned long long dup_pack(float f) {
    unsigned int b = __builtin_bit_cast(unsigned int, f);
    return (unsigned long long)b | ((unsigned long long)b << 32);
}
struct CkTables {
    unsigned long long ck1[N_ITERS];   // 1 + ck
    unsigned long long nck[N_ITERS];   // -ck
    constexpr CkTables() : ck1{}, nck{} {
        double t = 1.0;
        for (int i = 0; i < N_ITERS; ++i) {
            double tn = 0.5 * (1.0 + csqrt(1.0 + 4.0 * t * t));
            float ck = (float)((t - 1.0) / tn);
            ck1[i] = dup_pack(1.0f + ck);
            nck[i] = dup_pack(-ck);
            t = tn;
        }
    }
};
__constant__ CkTables CKT = CkTables();

using u64 = unsigned long long;

__device__ __forceinline__ u64 pk2(float lo, float hi) {
    u64 r; asm("mov.b64 %0,{%1,%2};" : "=l"(r) : "f"(lo), "f"(hi)); return r;
}
__device__ __forceinline__ void upk2(u64 v, float& lo, float& hi) {
    asm("mov.b64 {%0,%1},%2;" : "=f"(lo), "=f"(hi) : "l"(v));
}
__device__ __forceinline__ u64 f2fma(u64 a, u64 b, u64 c) {   // a*b + c (packed)
    u64 d; asm("fma.rn.f32x2 %0,%1,%2,%3;" : "=l"(d) : "l"(a), "l"(b), "l"(c)); return d;
}
__device__ __forceinline__ u64 f2mul(u64 a, u64 b) {
    u64 d; asm("mul.rn.f32x2 %0,%1,%2;" : "=l"(d) : "l"(a), "l"(b)); return d;
}
__device__ __forceinline__ u64 f2add(u64 a, u64 b) {
    u64 d; asm("add.rn.f32x2 %0,%1,%2;" : "=l"(d) : "l"(a), "l"(b)); return d;
}

__device__ __forceinline__ void fista_pass(const float ys[EPT], const u64 ycP[NP],
                                           u64 xP[NP], int lane)
{
    const bool L = (lane == 0), R = (lane == 31);
    const u64 C0P = pk2(C0c, C0c);
    const u64 C1P = pk2(C1c, C1c);
    const u64 C2P = pk2(C2c, C2c);

    // x0 = proj(y) = y identically (min(max(y,0),y) == y)
    u64 zP[NP];
#pragma unroll
    for (int j = 0; j < NP; ++j) { xP[j] = pk2(ys[j], ys[j + 8]); zP[j] = xP[j]; }

#pragma unroll 1
    for (int it = 0; it < N_ITERS; ++it) {
        const u64 ck1P = CKT.ck1[it];
        const u64 nckP = CKT.nck[it];

        // scalar views for halos / ghosts / seams
        float z0, z8, z1, z9, z6, z14, z7, z15;
        upk2(zP[0], z0, z8);
        upk2(zP[1], z1, z9);
        upk2(zP[6], z6, z14);
        upk2(zP[7], z7, z15);

        float zm1  = __shfl_up_sync  (0xffffffffu, z15, 1);   // z[-1]
        float zm2  = __shfl_up_sync  (0xffffffffu, z14, 1);   // z[-2]
        float zp16 = __shfl_down_sync(0xffffffffu, z0,  1);   // z[16]
        float zp17 = __shfl_down_sync(0xffffffffu, z1,  1);   // z[17]

        // ghost points (linear extrapolation == exact DtD boundary rows)
        {
            float a  = z0 - z1;
            float g1 = z0 + a;
            float g2 = g1 + a;
            if (L) { zm1 = g1; zm2 = g2; }
            float b  = z15 - z14;
            float h1 = z15 + b;
            float h2 = h1 + b;
            if (R) { zp16 = h1; zp17 = h2; }
        }

        // extended pair array: PP[j+2] covers pair positions j = -2 .. 9
        u64 PP[NP + 4];
        PP[0] = pk2(zm2, z6);        // (z[-2], z[6])
        PP[1] = pk2(zm1, z7);        // (z[-1], z[7])
#pragma unroll
        for (int j = 0; j < NP; ++j) PP[j + 2] = zP[j];
        PP[10] = pk2(z8, zp16);      // (z[8],  z[16])
        PP[11] = pk2(z9, zp17);      // (z[9],  z[17])

#pragma unroll
        for (int j = 0; j < NP; ++j) {
            // symmetric stencil: v = yc + C0*(Pm2+Pp2) + C1*(Pm1+Pp1) + C2*Pc
            u64 s0 = f2add(PP[j],     PP[j + 4]);
            u64 s1 = f2add(PP[j + 1], PP[j + 3]);
            u64 v  = f2fma(C0P, s0, ycP[j]);
            v      = f2fma(C1P, s1, v);
            v      = f2fma(C2P, PP[j + 2], v);

            // momentum helper independent of the clamp chain
            u64 t  = f2mul(nckP, xP[j]);          // -ck * x_old

            float vl, vh;
            upk2(v, vl, vh);
            vl = fminf(fmaxf(vl, 0.0f), ys[j]);
            vh = fminf(fmaxf(vh, 0.0f), ys[j + 8]);
            u64 xn = pk2(vl, vh);

            zP[j] = f2fma(ck1P, xn, t);           // (1+ck)*xn - ck*x_old
            xP[j] = xn;
        }
    }
}

__global__ void __launch_bounds__(TPB, 5)
denoise_fista_kernel(const float* __restrict__ in, float* __restrict__ out, int nrows)
{
    const int warp = blockIdx.x * (TPB / 32) + (threadIdx.x >> 5);
    const int lane = threadIdx.x & 31;
    if (warp >= nrows) return;

    const float4* src = reinterpret_cast<const float4*>(in + (size_t)warp * ROWLEN + lane * EPT);
    float ys[EPT];
    {
        float4 a = src[0], b = src[1], c = src[2], d4 = src[3];
        ys[0] = a.x;  ys[1] = a.y;  ys[2]  = a.z;  ys[3]  = a.w;
        ys[4] = b.x;  ys[5] = b.y;  ys[6]  = b.z;  ys[7]  = b.w;
        ys[8] = c.x;  ys[9] = c.y;  ys[10] = c.z;  ys[11] = c.w;
        ys[12] = d4.x; ys[13] = d4.y; ys[14] = d4.z; ys[15] = d4.w;
    }

    u64 ycP[NP];
    const u64 CBP = pk2(CBc, CBc);
#pragma unroll
    for (int j = 0; j < NP; ++j) ycP[j] = f2mul(CBP, pk2(ys[j], ys[j + 8]));

    u64 xP[NP];
    fista_pass(ys, ycP, xP, lane);        // pass 1: y = input

    float ys2[EPT];
    u64 ycP2[NP];
#pragma unroll
    for (int j = 0; j < NP; ++j) {
        float lo, hi;
        upk2(xP[j], lo, hi);
        ys2[j] = lo; ys2[j + 8] = hi;
        ycP2[j] = f2mul(CBP, xP[j]);
    }
    fista_pass(ys2, ycP2, xP, lane);      // pass 2: y = pass-1 output

    float xo[EPT];
#pragma unroll
    for (int j = 0; j < NP; ++j) {
        float lo, hi;
        upk2(xP[j], lo, hi);
        xo[j] = lo; xo[j + 8] = hi;
    }

    float4* dst = reinterpret_cast<float4*>(out + (size_t)warp * ROWLEN + lane * EPT);
    float4 a, b, c, d4;
    a.x = xo[0];  a.y = xo[1];  a.z = xo[2];   a.w = xo[3];
    b.x = xo[4];  b.y = xo[5];  b.z = xo[6];   b.w = xo[7];
    c.x = xo[8];  c.y = xo[9];  c.z = xo[10];  c.w = xo[11];
    d4.x = xo[12]; d4.y = xo[13]; d4.z = xo[14]; d4.w = xo[15];
    dst[0] = a; dst[1] = b; dst[2] = c; dst[3] = d4;
}

extern "C" void kernel_launch(void* const* d_in, const int* in_sizes, int n_in,
                              void* d_out, int out_size)
{
    const float* in  = (const float*)d_in[0];
    float*       out = (float*)d_out;
    const int nrows  = in_sizes[0] / ROWLEN;            // 16384
    const int rows_per_block = TPB / 32;                // 4
    const int grid = (nrows + rows_per_block - 1) / rows_per_block;
    denoise_fista_kernel<<<grid, TPB>>>(in, out, nrows);
}